// round 7
// baseline (speedup 1.0000x reference)
#include <cuda_runtime.h>
#include <stdint.h>

// ---------------------------------------------------------------------------
//   vit_feature : (B=16, D=256, R=1024)  f32
//   lag_feature : (B=16, S=20,  D=256)   f32
//   lag_vit_map : (B=16, S=20,  R=1024)  f32
// out (concat f32): vit_corr (R,B,D) | lag_corr (R,B,4,D) | neg (R,B,5,D)
// ---------------------------------------------------------------------------

#define B_ 16
#define D_ 256
#define R_ 1024
#define S_ 20
#define TOPK_ 4
#define NEGN_ 5

static __device__ int   g_cols[B_ * R_ * TOPK_];
static __device__ float g_vit15[R_ * D_];   // vit[b=15] transposed: [r][d]

// ---------------- threefry-2x32, JAX partitionable 32-bit path --------------
__device__ __forceinline__ uint32_t rotl32(uint32_t x, int r) {
    return __funnelshift_l(x, x, r);  // SHF (alu pipe, unavoidable)
}

// add issued as IMAD on the FMA pipe: d = a*one + c, with `one` a
// runtime-opaque register equal to 1 (ptxas cannot strength-reduce it).
__device__ __forceinline__ uint32_t imad_add(uint32_t a, uint32_t one,
                                             uint32_t c) {
    uint32_t d;
    asm("mad.lo.u32 %0, %1, %2, %3;" : "=r"(d) : "r"(a), "r"(one), "r"(c));
    return d;
}

__device__ __forceinline__ uint32_t threefry_bits(uint32_t ctr_lo,
                                                  uint32_t one) {
    const uint32_t K0 = 0u;
    const uint32_t K1 = 1234u;
    const uint32_t K2 = 0x1BD11BDAu ^ K0 ^ K1;
    uint32_t ks[3] = {K0, K1, K2};
    uint32_t x0 = 0u + K0;
    uint32_t x1 = ctr_lo + K1;
    const int ROT0[4] = {13, 15, 26, 6};
    const int ROT1[4] = {17, 29, 16, 24};
#pragma unroll
    for (int i = 0; i < 5; ++i) {
#pragma unroll
        for (int j = 0; j < 4; ++j) {
            int r = (i & 1) ? ROT1[j] : ROT0[j];
            x0 = imad_add(x1, one, x0);  // FMA pipe
            x1 = rotl32(x1, r);          // ALU pipe
            x1 ^= x0;                    // ALU pipe
        }
        x0 = imad_add(ks[(i + 1) % 3], one, x0);                      // FMA
        x1 = imad_add(ks[(i + 2) % 3] + (uint32_t)(i + 1), one, x1);  // FMA
    }
    return x0 ^ x1;
}

__device__ __forceinline__ unsigned long long warp_max_ull(unsigned long long v) {
#pragma unroll
    for (int o = 16; o > 0; o >>= 1) {
        unsigned long long u = __shfl_xor_sync(0xffffffffu, v, o);
        v = (u > v) ? u : v;
    }
    return v;
}

#define INSERT5(k)                                          \
    do {                                                    \
        if ((k) > a4) {                                     \
            a4 = (k);                                       \
            unsigned long long _t;                          \
            if (a4 > a3) { _t = a3; a3 = a4; a4 = _t; }     \
            if (a3 > a2) { _t = a2; a2 = a3; a3 = _t; }     \
            if (a2 > a1) { _t = a1; a1 = a2; a2 = _t; }     \
            if (a1 > a0) { _t = a0; a0 = a1; a1 = _t; }     \
        }                                                   \
    } while (0)

// ---------------- Stage 1: vit[15] mini-transpose + top-4 cols --------------
__global__ void __launch_bounds__(128) stage1_kernel(
    const float* __restrict__ vit, const float* __restrict__ lvm) {
    int bid = blockIdx.x;
    int tid = threadIdx.x;
    if (bid < 256) {
        __shared__ float tile[32][33];
        int r0 = (bid & 31) * 32;
        int d0 = (bid >> 5) * 32;
        int tx = tid & 31, ty = tid >> 5;
        const float* src = vit + 15 * (D_ * R_);
#pragma unroll
        for (int k = 0; k < 8; ++k) {
            int dl = k * 4 + ty;
            tile[dl][tx] = src[(d0 + dl) * R_ + r0 + tx];
        }
        __syncthreads();
#pragma unroll
        for (int k = 0; k < 8; ++k) {
            int rl = k * 4 + ty;
            g_vit15[(r0 + rl) * D_ + d0 + tx] = tile[tx][rl];
        }
    } else {
        int t = (bid - 256) * 128 + tid;  // 0..16383
        int b = t >> 10;
        int r = t & (R_ - 1);
        const float* base = lvm + b * (S_ * R_) + r;
        unsigned long long a0 = 0, a1 = 0, a2 = 0, a3 = 0;
#pragma unroll
        for (int s = 0; s < S_; ++s) {
            uint32_t u = __float_as_uint(base[s * R_]);
            uint32_t m = u ^ (uint32_t)(((int32_t)u >> 31) | 0x80000000u);
            unsigned long long k =
                ((unsigned long long)m << 32) | (uint32_t)(~(uint32_t)s);
            if (k > a3) {
                a3 = k;
                unsigned long long _t;
                if (a3 > a2) { _t = a2; a2 = a3; a3 = _t; }
                if (a2 > a1) { _t = a1; a1 = a2; a2 = _t; }
                if (a1 > a0) { _t = a0; a0 = a1; a1 = _t; }
            }
        }
        int o = t * TOPK_;
        g_cols[o + 0] = (int)(~(uint32_t)a0);
        g_cols[o + 1] = (int)(~(uint32_t)a1);
        g_cols[o + 2] = (int)(~(uint32_t)a2);
        g_cols[o + 3] = (int)(~(uint32_t)a3);
    }
}

// ---------------- Stage 2: fat fused kernel ---------------------------------
//   bid%7 in {0..3} -> neg row   (16384 blocks)
//   bid%7 == 4      -> transpose tile (4096 blocks)
//   bid%7 in {5,6}  -> lag slab  (8192 blocks)
#define FAT_GRID (4096 * 7)
#define THRESH_ 0xFC000000u  // top 1/64: E[survivors/row]=16, P(<5)~4e-4

__global__ void __launch_bounds__(128) fat_kernel(
    const float* __restrict__ vit, const float4* __restrict__ lag4,
    float* __restrict__ out1, float4* __restrict__ out2_4,
    float4* __restrict__ out3_4) {
    int bid = blockIdx.x;
    int tid = threadIdx.x;
    int grp = bid / 7;
    int lane7 = bid - grp * 7;

    if (lane7 < 4) {
        // ---------------- neg role: one (r,b) row ----------------
        int rb = grp * 4 + lane7;
        int r = rb >> 4;
        int b = rb & 15;
        // runtime-opaque 1 (blockDim.x==128): keeps IMADs on the fma pipe
        uint32_t one = blockDim.x >> 7;

        __shared__ unsigned long long wkeys[4][5];
        __shared__ int sidx[5];
        __shared__ int scnt[4];

        unsigned long long a0 = 0, a1 = 0, a2 = 0, a3 = 0, a4 = 0;
        int cnt = 0;
        bool isb15 = (b == (B_ - 1));
#pragma unroll
        for (int it = 0; it < 8; ++it) {
            int r2 = tid + it * 128;
            uint32_t bits = threefry_bits((uint32_t)(rb * R_ + r2), one);
            bool ok = (bits >= THRESH_) && !(isb15 && (r2 == r));
            if (ok) {
                ++cnt;
                unsigned long long key =
                    ((unsigned long long)(bits >> 9) << 32) |
                    (uint32_t)(~(uint32_t)r2);
                INSERT5(key);
            }
        }
#pragma unroll
        for (int o = 16; o > 0; o >>= 1) cnt += __shfl_xor_sync(0xffffffffu, cnt, o);
        int wid = tid >> 5;
        if ((tid & 31) == 0) scnt[wid] = cnt;
        __syncthreads();
        int total = scnt[0] + scnt[1] + scnt[2] + scnt[3];
        if (total < NEGN_) {  // astronomically rare; exact rescan
            a0 = a1 = a2 = a3 = a4 = 0;
#pragma unroll
            for (int it = 0; it < 8; ++it) {
                int r2 = tid + it * 128;
                uint32_t bits = threefry_bits((uint32_t)(rb * R_ + r2), one);
                if (!(isb15 && (r2 == r))) {
                    unsigned long long key =
                        ((unsigned long long)(bits >> 9) << 32) |
                        (uint32_t)(~(uint32_t)r2);
                    INSERT5(key);
                }
            }
        }
        // warp-level: pop warp max 5 times (nonzero keys globally unique)
#pragma unroll
        for (int j = 0; j < NEGN_; ++j) {
            unsigned long long m = warp_max_ull(a0);
            if (a0 == m) { a0 = a1; a1 = a2; a2 = a3; a3 = a4; a4 = 0; }
            if ((tid & 31) == 0) wkeys[wid][j] = m;
        }
        __syncthreads();
        if (tid < 32) {
            unsigned long long k = 0;
            if (tid < 20) k = wkeys[tid / 5][tid % 5];
#pragma unroll
            for (int j = 0; j < NEGN_; ++j) {
                unsigned long long m = warp_max_ull(k);
                if (k == m) k = 0;
                if (tid == 0) sidx[j] = (int)(~(uint32_t)m);
            }
        }
        __syncthreads();
        const float4* v15 = (const float4*)g_vit15;
        for (int t = tid; t < NEGN_ * (D_ / 4); t += 128) {
            int n = t >> 6;
            int f = t & 63;
            out3_4[(rb * NEGN_ + n) * (D_ / 4) + f] = v15[sidx[n] * 64 + f];
        }
    } else if (lane7 == 4) {
        // ---------------- transpose role: one 32x32 tile ----------------
        __shared__ float tile[32][33];
        int b = grp >> 8;
        int rem = grp & 255;
        int r0 = (rem & 31) * 32;
        int d0 = (rem >> 5) * 32;
        int tx = tid & 31, ty = tid >> 5;
        const float* src = vit + b * (D_ * R_);
#pragma unroll
        for (int k = 0; k < 8; ++k) {
            int dl = k * 4 + ty;
            tile[dl][tx] = src[(d0 + dl) * R_ + r0 + tx];
        }
        __syncthreads();
#pragma unroll
        for (int k = 0; k < 8; ++k) {
            int rl = k * 4 + ty;
            out1[((r0 + rl) * B_ + b) * D_ + d0 + tx] = tile[tx][rl];
        }
    } else {
        // ---------------- lag role: 512 consecutive float4 of out2 ------
        int li = grp * 2 + (lane7 - 5);  // 0..8191
        int base = li * 512;
#pragma unroll
        for (int j = 0; j < 4; ++j) {
            int t = base + j * 128 + tid;
            int rid = t >> 6;  // (r*16+b)*4+k
            int f = t & 63;
            int k = rid & 3;
            int b = (rid >> 2) & 15;
            int r = rid >> 6;
            int col = g_cols[(((b << 10) + r) << 2) + k];
            out2_4[t] = lag4[(b * S_ + col) * (D_ / 4) + f];
        }
    }
}

// ---------------------------------------------------------------------------
extern "C" void kernel_launch(void* const* d_in, const int* in_sizes, int n_in,
                              void* d_out, int out_size) {
    const float* vit = (const float*)d_in[0];
    const float* lag = (const float*)d_in[1];
    const float* lvm = (const float*)d_in[2];
    float* out = (float*)d_out;

    float* out1 = out;                                  // R*B*D
    float* out2 = out1 + (size_t)R_ * B_ * D_;          // R*B*4*D
    float* out3 = out2 + (size_t)R_ * B_ * TOPK_ * D_;  // R*B*5*D

    stage1_kernel<<<384, 128>>>(vit, lvm);
    fat_kernel<<<FAT_GRID, 128>>>(vit, (const float4*)lag, out1,
                                  (float4*)out2, (float4*)out3);
}

// round 9
// speedup vs baseline: 1.1980x; 1.1980x over previous
#include <cuda_runtime.h>
#include <stdint.h>

// ---------------------------------------------------------------------------
//   vit_feature : (B=16, D=256, R=1024)  f32
//   lag_feature : (B=16, S=20,  D=256)   f32
//   lag_vit_map : (B=16, S=20,  R=1024)  f32
// out (concat f32): vit_corr (R,B,D) | lag_corr (R,B,4,D) | neg (R,B,5,D)
// ---------------------------------------------------------------------------

#define B_ 16
#define D_ 256
#define R_ 1024
#define S_ 20
#define TOPK_ 4
#define NEGN_ 5

static __device__ int   g_cols[B_ * R_ * TOPK_];
static __device__ float g_vit15[R_ * D_];   // vit[b=15] transposed: [r][d]

// ---------------- threefry-2x32, JAX partitionable 32-bit path --------------
__device__ __forceinline__ uint32_t rotl32(uint32_t x, int r) {
    return __funnelshift_l(x, x, r);
}

__device__ __forceinline__ uint32_t threefry_bits(uint32_t ctr_lo) {
    const uint32_t K0 = 0u;
    const uint32_t K1 = 1234u;
    const uint32_t K2 = 0x1BD11BDAu ^ K0 ^ K1;
    uint32_t ks[3] = {K0, K1, K2};
    uint32_t x0 = 0u + K0;
    uint32_t x1 = ctr_lo + K1;
    const int ROT0[4] = {13, 15, 26, 6};
    const int ROT1[4] = {17, 29, 16, 24};
#pragma unroll
    for (int i = 0; i < 5; ++i) {
#pragma unroll
        for (int j = 0; j < 3; ++j) {
            int r = (i & 1) ? ROT1[j] : ROT0[j];
            x0 += x1;
            x1 = rotl32(x1, r);
            x1 ^= x0;
        }
        // 4th mix fused with key-schedule add (IADD3-friendly shapes)
        int r4 = (i & 1) ? ROT1[3] : ROT0[3];
        uint32_t xr = rotl32(x1, r4);
        x0 = (x0 + x1) + ks[(i + 1) % 3];
        x1 = (xr ^ (x0 - ks[(i + 1) % 3])) + (ks[(i + 2) % 3] + (uint32_t)(i + 1));
        // note: xr must xor with pre-key x0; recompute via subtract keeps
        // correctness while exposing IADD3 fusion on the x0 update.
    }
    return x0 ^ x1;
}

__device__ __forceinline__ unsigned long long warp_max_ull(unsigned long long v) {
#pragma unroll
    for (int o = 16; o > 0; o >>= 1) {
        unsigned long long u = __shfl_xor_sync(0xffffffffu, v, o);
        v = (u > v) ? u : v;
    }
    return v;
}

#define INSERT5(k)                                          \
    do {                                                    \
        if ((k) > a4) {                                     \
            a4 = (k);                                       \
            unsigned long long _t;                          \
            if (a4 > a3) { _t = a3; a3 = a4; a4 = _t; }     \
            if (a3 > a2) { _t = a2; a2 = a3; a3 = _t; }     \
            if (a2 > a1) { _t = a1; a1 = a2; a2 = _t; }     \
            if (a1 > a0) { _t = a0; a0 = a1; a1 = _t; }     \
        }                                                   \
    } while (0)

// ---------------- Stage 1: vit[15] mini-transpose + top-4 cols --------------
__global__ void __launch_bounds__(128) stage1_kernel(
    const float* __restrict__ vit, const float* __restrict__ lvm) {
    int bid = blockIdx.x;
    int tid = threadIdx.x;
    if (bid < 256) {
        __shared__ float tile[32][33];
        int r0 = (bid & 31) * 32;
        int d0 = (bid >> 5) * 32;
        int tx = tid & 31, ty = tid >> 5;
        const float* src = vit + 15 * (D_ * R_);
#pragma unroll
        for (int k = 0; k < 8; ++k) {
            int dl = k * 4 + ty;
            tile[dl][tx] = src[(d0 + dl) * R_ + r0 + tx];
        }
        __syncthreads();
#pragma unroll
        for (int k = 0; k < 8; ++k) {
            int rl = k * 4 + ty;
            g_vit15[(r0 + rl) * D_ + d0 + tx] = tile[tx][rl];
        }
    } else {
        int t = (bid - 256) * 128 + tid;  // 0..16383
        int b = t >> 10;
        int r = t & (R_ - 1);
        const float* base = lvm + b * (S_ * R_) + r;
        unsigned long long a0 = 0, a1 = 0, a2 = 0, a3 = 0;
#pragma unroll
        for (int s = 0; s < S_; ++s) {
            uint32_t u = __float_as_uint(base[s * R_]);
            uint32_t m = u ^ (uint32_t)(((int32_t)u >> 31) | 0x80000000u);
            unsigned long long k =
                ((unsigned long long)m << 32) | (uint32_t)(~(uint32_t)s);
            if (k > a3) {
                a3 = k;
                unsigned long long _t;
                if (a3 > a2) { _t = a2; a2 = a3; a3 = _t; }
                if (a2 > a1) { _t = a1; a1 = a2; a2 = _t; }
                if (a1 > a0) { _t = a0; a0 = a1; a1 = _t; }
            }
        }
        int o = t * TOPK_;
        g_cols[o + 0] = (int)(~(uint32_t)a0);
        g_cols[o + 1] = (int)(~(uint32_t)a1);
        g_cols[o + 2] = (int)(~(uint32_t)a2);
        g_cols[o + 3] = (int)(~(uint32_t)a3);
    }
}

// ---------------- Stage 2: fat fused kernel ---------------------------------
//   bid%7 in {0..3} -> neg row   (16384 blocks)
//   bid%7 == 4      -> transpose tile (4096 blocks)
//   bid%7 in {5,6}  -> lag slab  (8192 blocks)
#define FAT_GRID (4096 * 7)
#define THRESH_ 0xFC000000u  // top 1/64: E[survivors/row]=16
#define MAXSURV_ 64

__global__ void __launch_bounds__(128) fat_kernel(
    const float* __restrict__ vit, const float4* __restrict__ lag4,
    float* __restrict__ out1, float4* __restrict__ out2_4,
    float4* __restrict__ out3_4) {
    int bid = blockIdx.x;
    int tid = threadIdx.x;
    int grp = bid / 7;
    int lane7 = bid - grp * 7;

    if (lane7 < 4) {
        // ---------------- neg role: one (r,b) row ----------------
        int rb = grp * 4 + lane7;
        int r = rb >> 4;
        int b = rb & 15;
        bool isb15 = (b == (B_ - 1));

        __shared__ unsigned long long skeys[MAXSURV_];
        __shared__ int sn;
        __shared__ int sidx[NEGN_];

        if (tid == 0) sn = 0;
        __syncthreads();

        // hot scan: threefry + threshold + rare atomic push
        uint32_t cbase = (uint32_t)(rb * R_);
#pragma unroll
        for (int it = 0; it < 8; ++it) {
            int r2 = tid + it * 128;
            uint32_t bits = threefry_bits(cbase + (uint32_t)r2);
            if (bits >= THRESH_) {
                if (!(isb15 && (r2 == r))) {
                    int slot = atomicAdd(&sn, 1);
                    if (slot < MAXSURV_) {
                        skeys[slot] =
                            ((unsigned long long)(bits >> 9) << 32) |
                            (uint32_t)(~(uint32_t)r2);
                    }
                }
            }
        }
        __syncthreads();
        int total = sn;

        if (total >= NEGN_ && total <= MAXSURV_) {
            // fast select: warp 0, <=64 unique nonzero keys, pop max 5 times
            if (tid < 32) {
                unsigned long long k1 = (tid < total) ? skeys[tid] : 0ull;
                unsigned long long k2 =
                    (tid + 32 < total) ? skeys[tid + 32] : 0ull;
#pragma unroll
                for (int j = 0; j < NEGN_; ++j) {
                    unsigned long long v = (k1 > k2) ? k1 : k2;
                    unsigned long long m = warp_max_ull(v);
                    if (m == k1) k1 = 0ull;
                    else if (m == k2) k2 = 0ull;
                    if (tid == 0) sidx[j] = (int)(~(uint32_t)m);
                }
            }
        } else {
            // exact cold fallback: per-thread INSERT5 over all 1024
            __shared__ unsigned long long wkeys[4][NEGN_];
            unsigned long long a0 = 0, a1 = 0, a2 = 0, a3 = 0, a4 = 0;
#pragma unroll
            for (int it = 0; it < 8; ++it) {
                int r2 = tid + it * 128;
                uint32_t bits = threefry_bits(cbase + (uint32_t)r2);
                if (!(isb15 && (r2 == r))) {
                    unsigned long long key =
                        ((unsigned long long)(bits >> 9) << 32) |
                        (uint32_t)(~(uint32_t)r2);
                    INSERT5(key);
                }
            }
            int wid = tid >> 5;
#pragma unroll
            for (int j = 0; j < NEGN_; ++j) {
                unsigned long long m = warp_max_ull(a0);
                if (a0 == m) { a0 = a1; a1 = a2; a2 = a3; a3 = a4; a4 = 0; }
                if ((tid & 31) == 0) wkeys[wid][j] = m;
            }
            __syncthreads();
            if (tid < 32) {
                unsigned long long k = 0;
                if (tid < 20) k = wkeys[tid / 5][tid % 5];
#pragma unroll
                for (int j = 0; j < NEGN_; ++j) {
                    unsigned long long m = warp_max_ull(k);
                    if (k == m) k = 0;
                    if (tid == 0) sidx[j] = (int)(~(uint32_t)m);
                }
            }
        }
        __syncthreads();

        const float4* v15 = (const float4*)g_vit15;
        for (int t = tid; t < NEGN_ * (D_ / 4); t += 128) {
            int n = t >> 6;
            int f = t & 63;
            out3_4[(rb * NEGN_ + n) * (D_ / 4) + f] = v15[sidx[n] * 64 + f];
        }
    } else if (lane7 == 4) {
        // ---------------- transpose role: one 32x32 tile ----------------
        __shared__ float tile[32][33];
        int b = grp >> 8;
        int rem = grp & 255;
        int r0 = (rem & 31) * 32;
        int d0 = (rem >> 5) * 32;
        int tx = tid & 31, ty = tid >> 5;
        const float* src = vit + b * (D_ * R_);
#pragma unroll
        for (int k = 0; k < 8; ++k) {
            int dl = k * 4 + ty;
            tile[dl][tx] = src[(d0 + dl) * R_ + r0 + tx];
        }
        __syncthreads();
#pragma unroll
        for (int k = 0; k < 8; ++k) {
            int rl = k * 4 + ty;
            out1[((r0 + rl) * B_ + b) * D_ + d0 + tx] = tile[tx][rl];
        }
    } else {
        // ---------------- lag role: 512 consecutive float4 of out2 ------
        int li = grp * 2 + (lane7 - 5);  // 0..8191
        int base = li * 512;
#pragma unroll
        for (int j = 0; j < 4; ++j) {
            int t = base + j * 128 + tid;
            int rid = t >> 6;  // (r*16+b)*4+k
            int f = t & 63;
            int k = rid & 3;
            int b = (rid >> 2) & 15;
            int r = rid >> 6;
            int col = g_cols[(((b << 10) + r) << 2) + k];
            out2_4[t] = lag4[(b * S_ + col) * (D_ / 4) + f];
        }
    }
}

// ---------------------------------------------------------------------------
extern "C" void kernel_launch(void* const* d_in, const int* in_sizes, int n_in,
                              void* d_out, int out_size) {
    const float* vit = (const float*)d_in[0];
    const float* lag = (const float*)d_in[1];
    const float* lvm = (const float*)d_in[2];
    float* out = (float*)d_out;

    float* out1 = out;                                  // R*B*D
    float* out2 = out1 + (size_t)R_ * B_ * D_;          // R*B*4*D
    float* out3 = out2 + (size_t)R_ * B_ * TOPK_ * D_;  // R*B*5*D

    stage1_kernel<<<384, 128>>>(vit, lvm);
    fat_kernel<<<FAT_GRID, 128>>>(vit, (const float4*)lag, out1,
                                  (float4*)out2, (float4*)out3);
}

// round 11
// speedup vs baseline: 1.2706x; 1.0606x over previous
#include <cuda_runtime.h>
#include <stdint.h>

// ---------------------------------------------------------------------------
//   vit_feature : (B=16, D=256, R=1024)  f32
//   lag_feature : (B=16, S=20,  D=256)   f32
//   lag_vit_map : (B=16, S=20,  R=1024)  f32
// out (concat f32): vit_corr (R,B,D) | lag_corr (R,B,4,D) | neg (R,B,5,D)
// ---------------------------------------------------------------------------

#define B_ 16
#define D_ 256
#define R_ 1024
#define S_ 20
#define TOPK_ 4
#define NEGN_ 5

static __device__ float g_vit15[R_ * D_];   // vit[b=15] transposed: [r][d]

// ---------------- threefry-2x32, JAX partitionable 32-bit path --------------
__device__ __forceinline__ uint32_t rotl32(uint32_t x, int r) {
    return __funnelshift_l(x, x, r);
}

__device__ __forceinline__ uint32_t threefry_bits(uint32_t ctr_lo) {
    const uint32_t K0 = 0u;
    const uint32_t K1 = 1234u;
    const uint32_t K2 = 0x1BD11BDAu ^ K0 ^ K1;
    uint32_t ks[3] = {K0, K1, K2};
    uint32_t x0 = 0u + K0;
    uint32_t x1 = ctr_lo + K1;
    const int ROT0[4] = {13, 15, 26, 6};
    const int ROT1[4] = {17, 29, 16, 24};
#pragma unroll
    for (int i = 0; i < 5; ++i) {
#pragma unroll
        for (int j = 0; j < 3; ++j) {
            int r = (i & 1) ? ROT1[j] : ROT0[j];
            x0 += x1;
            x1 = rotl32(x1, r);
            x1 ^= x0;
        }
        // 4th mix fused with key-schedule add (IADD3-friendly shapes)
        int r4 = (i & 1) ? ROT1[3] : ROT0[3];
        uint32_t xr = rotl32(x1, r4);
        x0 = (x0 + x1) + ks[(i + 1) % 3];
        x1 = (xr ^ (x0 - ks[(i + 1) % 3])) + (ks[(i + 2) % 3] + (uint32_t)(i + 1));
    }
    return x0 ^ x1;
}

__device__ __forceinline__ unsigned long long warp_max_ull(unsigned long long v) {
#pragma unroll
    for (int o = 16; o > 0; o >>= 1) {
        unsigned long long u = __shfl_xor_sync(0xffffffffu, v, o);
        v = (u > v) ? u : v;
    }
    return v;
}

#define INSERT5(k)                                          \
    do {                                                    \
        if ((k) > a4) {                                     \
            a4 = (k);                                       \
            unsigned long long _t;                          \
            if (a4 > a3) { _t = a3; a3 = a4; a4 = _t; }     \
            if (a3 > a2) { _t = a2; a2 = a3; a3 = _t; }     \
            if (a2 > a1) { _t = a1; a1 = a2; a2 = _t; }     \
            if (a1 > a0) { _t = a0; a0 = a1; a1 = _t; }     \
        }                                                   \
    } while (0)

// ---------------- Stage 1: vit[15] mini-transpose only ----------------------
__global__ void __launch_bounds__(128) stage1_kernel(
    const float* __restrict__ vit) {
    int bid = blockIdx.x;
    int tid = threadIdx.x;
    __shared__ float tile[32][33];
    int r0 = (bid & 31) * 32;
    int d0 = (bid >> 5) * 32;
    int tx = tid & 31, ty = tid >> 5;
    const float* src = vit + 15 * (D_ * R_);
#pragma unroll
    for (int k = 0; k < 8; ++k) {
        int dl = k * 4 + ty;
        tile[dl][tx] = src[(d0 + dl) * R_ + r0 + tx];
    }
    __syncthreads();
#pragma unroll
    for (int k = 0; k < 8; ++k) {
        int rl = k * 4 + ty;
        g_vit15[(r0 + rl) * D_ + d0 + tx] = tile[tx][rl];
    }
}

// ---------------- Stage 2: fat fused kernel ---------------------------------
// 4096 groups x 5 roles:
//   lane5 in {0,1} -> neg block, 2 rows each  (8192 blocks, 16384 rows)
//   lane5 == 2     -> transpose tile          (4096 blocks)
//   lane5 in {3,4} -> lag slab (512 f4) w/ inline top-4 cols (8192 blocks)
#define FAT_GRID (4096 * 5)
#define THRESH_ 0xFC000000u  // top 1/64: E[survivors/row]=16
#define MAXSURV_ 64

__global__ void __launch_bounds__(128) fat_kernel(
    const float* __restrict__ vit, const float4* __restrict__ lag4,
    const float* __restrict__ lvm, float* __restrict__ out1,
    float4* __restrict__ out2_4, float4* __restrict__ out3_4) {
    int bid = blockIdx.x;
    int tid = threadIdx.x;
    int grp = bid / 5;
    int lane5 = bid - grp * 5;

    if (lane5 < 2) {
        // ---------------- neg role: two (r,b) rows ----------------
        int rb0 = grp * 4 + lane5 * 2;  // rows rb0, rb0+1

        __shared__ unsigned long long skeys[2][MAXSURV_];
        __shared__ int sn[2];
        __shared__ int sidx[2][NEGN_];

        if (tid < 2) sn[tid] = 0;
        __syncthreads();

        // hot scan: 2 rows x 8 evals/thread
        for (int w = 0; w < 2; ++w) {
            int rb = rb0 + w;
            int r = rb >> 4;
            bool isb15 = ((rb & 15) == (B_ - 1));
            uint32_t cbase = (uint32_t)(rb << 10);
#pragma unroll
            for (int it = 0; it < 8; ++it) {
                int r2 = tid + it * 128;
                uint32_t bits = threefry_bits(cbase + (uint32_t)r2);
                if (bits >= THRESH_) {
                    if (!(isb15 && (r2 == r))) {
                        int slot = atomicAdd(&sn[w], 1);
                        if (slot < MAXSURV_) {
                            skeys[w][slot] =
                                ((unsigned long long)(bits >> 9) << 32) |
                                (uint32_t)(~(uint32_t)r2);
                        }
                    }
                }
            }
        }
        __syncthreads();

        // fast select: warp w selects top-5 of row w (<=64 unique keys)
        int wid = tid >> 5, lane = tid & 31;
        if (wid < 2) {
            int total = sn[wid];
            if (total >= NEGN_ && total <= MAXSURV_) {
                unsigned long long k1 =
                    (lane < total) ? skeys[wid][lane] : 0ull;
                unsigned long long k2 =
                    (lane + 32 < total) ? skeys[wid][lane + 32] : 0ull;
#pragma unroll
                for (int j = 0; j < NEGN_; ++j) {
                    unsigned long long v = (k1 > k2) ? k1 : k2;
                    unsigned long long m = warp_max_ull(v);
                    if (m == k1) k1 = 0ull;
                    else if (m == k2) k2 = 0ull;
                    if (lane == 0) sidx[wid][j] = (int)(~(uint32_t)m);
                }
            }
        }
        __syncthreads();

        // exact cold fallback per row (block-uniform condition, rare)
        for (int w = 0; w < 2; ++w) {
            int total = sn[w];
            if (total < NEGN_ || total > MAXSURV_) {
                unsigned long long* wk = &skeys[w][0];  // reuse as scratch
                int rb = rb0 + w;
                int r = rb >> 4;
                bool isb15 = ((rb & 15) == (B_ - 1));
                uint32_t cbase = (uint32_t)(rb << 10);
                unsigned long long a0 = 0, a1 = 0, a2 = 0, a3 = 0, a4 = 0;
#pragma unroll
                for (int it = 0; it < 8; ++it) {
                    int r2 = tid + it * 128;
                    uint32_t bits = threefry_bits(cbase + (uint32_t)r2);
                    if (!(isb15 && (r2 == r))) {
                        unsigned long long key =
                            ((unsigned long long)(bits >> 9) << 32) |
                            (uint32_t)(~(uint32_t)r2);
                        INSERT5(key);
                    }
                }
#pragma unroll
                for (int j = 0; j < NEGN_; ++j) {
                    unsigned long long m = warp_max_ull(a0);
                    if (a0 == m) { a0 = a1; a1 = a2; a2 = a3; a3 = a4; a4 = 0; }
                    if (lane == 0) wk[wid * NEGN_ + j] = m;
                }
                __syncthreads();
                if (tid < 32) {
                    unsigned long long k = 0;
                    if (tid < 4 * NEGN_) k = wk[tid];
#pragma unroll
                    for (int j = 0; j < NEGN_; ++j) {
                        unsigned long long m = warp_max_ull(k);
                        if (k == m) k = 0;
                        if (tid == 0) sidx[w][j] = (int)(~(uint32_t)m);
                    }
                }
                __syncthreads();
            }
        }

        // writes: 2 rows x 5 x 64 float4 = 640 f4, 5 iters
        const float4* v15 = (const float4*)g_vit15;
#pragma unroll
        for (int i = 0; i < 5; ++i) {
            int t = tid + i * 128;           // 0..639
            int w = (t >= 320) ? 1 : 0;
            int rem = t - w * 320;
            int n = rem >> 6;
            int f = rem & 63;
            out3_4[((rb0 + w) * NEGN_ + n) * (D_ / 4) + f] =
                v15[sidx[w][n] * 64 + f];
        }
    } else if (lane5 == 2) {
        // ---------------- transpose role: one 32x32 tile ----------------
        __shared__ float tile[32][33];
        int b = grp >> 8;
        int rem = grp & 255;
        int r0 = (rem & 31) * 32;
        int d0 = (rem >> 5) * 32;
        int tx = tid & 31, ty = tid >> 5;
        const float* src = vit + b * (D_ * R_);
#pragma unroll
        for (int k = 0; k < 8; ++k) {
            int dl = k * 4 + ty;
            tile[dl][tx] = src[(d0 + dl) * R_ + r0 + tx];
        }
        __syncthreads();
#pragma unroll
        for (int k = 0; k < 8; ++k) {
            int rl = k * 4 + ty;
            out1[((r0 + rl) * B_ + b) * D_ + d0 + tx] = tile[tx][rl];
        }
    } else {
        // ---------------- lag role: 512 f4 slab + inline top-4 cols -----
        int li = grp * 2 + (lane5 - 3);  // 0..8191; rows 2li, 2li+1
        __shared__ int scols[2][TOPK_];
        int wid = tid >> 5, lane = tid & 31;
        if (wid < 2) {
            int rb = 2 * li + wid;
            int b = rb & 15, r = rb >> 4;
            unsigned long long k = 0;
            if (lane < S_) {
                uint32_t u =
                    __float_as_uint(lvm[b * (S_ * R_) + lane * R_ + r]);
                uint32_t m = u ^ (uint32_t)(((int32_t)u >> 31) | 0x80000000u);
                k = ((unsigned long long)m << 32) |
                    (uint32_t)(~(uint32_t)lane);
            }
#pragma unroll
            for (int j = 0; j < TOPK_; ++j) {
                unsigned long long mx = warp_max_ull(k);
                if (k == mx) k = 0;
                if (lane == 0) scols[wid][j] = (int)(~(uint32_t)mx);
            }
        }
        __syncthreads();
        int base = li * 512;
#pragma unroll
        for (int j = 0; j < 4; ++j) {
            int lt = j * 128 + tid;          // 0..511
            int lrid = lt >> 6;              // 0..7 = w*4 + k
            int f = lt & 63;
            int k = lrid & 3;
            int w = lrid >> 2;
            int b = (2 * li + w) & 15;
            int col = scols[w][k];
            out2_4[base + lt] = lag4[(b * S_ + col) * (D_ / 4) + f];
        }
    }
}

// ---------------------------------------------------------------------------
extern "C" void kernel_launch(void* const* d_in, const int* in_sizes, int n_in,
                              void* d_out, int out_size) {
    const float* vit = (const float*)d_in[0];
    const float* lag = (const float*)d_in[1];
    const float* lvm = (const float*)d_in[2];
    float* out = (float*)d_out;

    float* out1 = out;                                  // R*B*D
    float* out2 = out1 + (size_t)R_ * B_ * D_;          // R*B*4*D
    float* out3 = out2 + (size_t)R_ * B_ * TOPK_ * D_;  // R*B*5*D

    stage1_kernel<<<256, 128>>>(vit);
    fat_kernel<<<FAT_GRID, 128>>>(vit, (const float4*)lag, lvm, out1,
                                  (float4*)out2, (float4*)out3);
}